// round 6
// baseline (speedup 1.0000x reference)
#include <cuda_runtime.h>
#include <cstdint>

// ============================================================================
// Fused ConvTranspose3d(32->64,k=5,s=2,p=2) + MaxPool(2) + MaxPool(3) + ch-sum
// == MaxPool(k=6,s=6) on y then sum. One CTA computes 2 adjacent w'-cells.
//
// R6: 768 threads = 24 warps; warp = (rd-parity P, rh, cell). acc halves to
// 18 f32x2 per thread -> 6 warps/SMSP for latency hiding. Template-specialized
// per (P,PH,CELL); per-SMSP class iteration sums balanced {38,38,38,36}.
// ============================================================================

#define THREADS 768
#define IC 32
#define OC 64
#define WT_PER_IC (125 * OC)             // 8000 floats
#define WT_TOTAL (IC * WT_PER_IC)        // 256000 floats (1.02 MB)
#define ICCH 2
#define NCH (IC / ICCH)                  // 16 chunks
#define CHUNK_FLOATS (ICCH * WT_PER_IC)  // 16000 floats (64 KB)
#define XS_FLOATS (IC * 5 * 5 * 8 * 2)   // 12800 floats (51.2 KB, duplicated)
#define SMEM_FLOATS (XS_FLOATS + 2 * CHUNK_FLOATS)   // 44800
#define SMEM_BYTES (SMEM_FLOATS * 4)     // 179200 B

__device__ __align__(16) float g_wt[WT_TOTAL];

// g_wt[ic][kd][kh][kw][oc]  <-  w[ic][oc][kd][kh][kw]
__global__ void wt_transpose_kernel(const float* __restrict__ w) {
    int idx = blockIdx.x * blockDim.x + threadIdx.x;
    if (idx >= WT_TOTAL) return;
    int oc = idx & 63;
    int t  = idx >> 6;
    int kw = t % 5;  t /= 5;
    int kh = t % 5;  t /= 5;
    int kd = t % 5;
    int ic = t / 5;
    g_wt[idx] = w[(((ic * OC + oc) * 5 + kd) * 5 + kh) * 5 + kw];
}

typedef unsigned long long ull;

__device__ __forceinline__ void ffma2(ull& a, ull xv, ull wv) {
    asm("fma.rn.f32x2 %0, %1, %2, %0;" : "+l"(a) : "l"(xv), "l"(wv));
}
__device__ __forceinline__ void cpa16(float* s, const float* g) {
    unsigned sa = (unsigned)__cvta_generic_to_shared(s);
    asm volatile("cp.async.cg.shared.global [%0], [%1], 16;" :: "r"(sa), "l"(g));
}
__device__ __forceinline__ void cp_commit() {
    asm volatile("cp.async.commit_group;");
}
__device__ __forceinline__ void cp_wait0() {
    asm volatile("cp.async.wait_group 0;" ::: "memory");
}
__device__ __forceinline__ float alo(ull a) {
    return __uint_as_float((unsigned)(a & 0xffffffffull));
}
__device__ __forceinline__ float ahi(ull a) {
    return __uint_as_float((unsigned)(a >> 32));
}

// Load the 5 duplicated x pairs this cell needs from a 16B-aligned row base.
// CELL 0: ull idx 0..4 (byte 0,8,16,24,32 from 16B-aligned row)
// CELL 1: ull idx 3..7 -> base xc is +24B, so (8B), (+8B:16B-al), (+24B)
template<int CELL>
__device__ __forceinline__ void load5(ull (&xp)[5], const float* xr) {
    if (CELL == 0) {
        ulonglong2 a = *(const ulonglong2*)(xr);
        ulonglong2 b = *(const ulonglong2*)(xr + 4);
        ull c = *(const ull*)(xr + 8);
        xp[0] = a.x; xp[1] = a.y; xp[2] = b.x; xp[3] = b.y; xp[4] = c;
    } else {
        ull a = *(const ull*)(xr);
        ulonglong2 b = *(const ulonglong2*)(xr + 2);
        ulonglong2 c = *(const ulonglong2*)(xr + 6);
        xp[0] = a; xp[1] = b.x; xp[2] = b.y; xp[3] = c.x; xp[4] = c.y;
    }
}

// ---------------------------------------------------------------------------
// Per-in-channel compute body, specialized on (P, PH, CELL).
// wic_l: weight base for this ic (incl. +2*lane oc offset)
// xc:    xs + ic*400 + q*16 + 6*CELL
// ---------------------------------------------------------------------------
template<int P, int PH, int CELL>
__device__ __forceinline__ void compute_ic(const float* __restrict__ wic_l,
                                           const float* __restrict__ xc,
                                           ull (&acc)[3][6]) {
    #pragma unroll
    for (int jh = 0; jh < 3 - PH; jh++) {
        const int kh = PH + 2 * jh;
        ull wv[3 - P][5];
        #pragma unroll
        for (int jd = 0; jd < 3 - P; jd++) {
            const int kd = P + 2 * jd;
            #pragma unroll
            for (int kw = 0; kw < 5; kw++)
                wv[jd][kw] =
                    *(const ull*)(wic_l + (((kd * 5 + kh) * 5 + kw) << 6));
        }
        #pragma unroll
        for (int ild = P; ild < 5; ild++) {
            const float* xr = xc + ild * 80 + (2 - jh) * 16;
            ull xp[5];
            load5<CELL>(xp, xr);
            #pragma unroll
            for (int jd = 0; jd < 3 - P; jd++) {
                const int ri = ild - 2 + jd;      // rd tile index
                if (ri < 0 || ri > 2) continue;   // compile-time pruned
                #pragma unroll
                for (int kw = 0; kw < 5; kw++) {
                    const int bw = (4 - kw + (kw & 1)) >> 1; // 2,2,1,1,0
                    #pragma unroll
                    for (int j = 0; j < 3; j++)
                        ffma2(acc[ri][(kw & 1) + 2 * j], xp[j + bw],
                              wv[jd][kw]);
                }
            }
        }
    }
}

extern __shared__ float smem_dyn[];

// wid -> (p, rh, cell); per-SMSP (wid&3) iteration sums {38,38,38,36}
__device__ __constant__ int c_p[24] =
    {0,0,0,0, 0,0,0,0, 0,0,1,0, 0,1,1,1, 1,1,1,1, 1,1,1,1};
__device__ __constant__ int c_rh[24] =
    {0,4,2,1, 2,0,4,3, 1,5,2,5, 3,0,4,0, 1,5,3,2, 3,1,5,4};
__device__ __constant__ int c_cell[24] =
    {0,0,1,1, 0,1,1,1, 0,0,0,1, 0,0,0,1, 0,0,1,1, 0,1,1,1};

__global__ void __launch_bounds__(THREADS, 1)
fused_kernel(const float* __restrict__ x,
             const float* __restrict__ bias,
             float* __restrict__ out) {
    float* xs  = smem_dyn;                // duplicated x tile [32][5][5][8]x2
    float* ws0 = smem_dyn + XS_FLOATS;    // weight double buffer

    const int px  = blockIdx.x;           // w'-pair: cells 2px, 2px+1
    const int ohp = blockIdx.y;
    const int b   = blockIdx.z / 5;
    const int odp = blockIdx.z % 5;
    const int tid = threadIdx.x;

    // ---- stage chunk 0 ----
    for (int j = tid; j < CHUNK_FLOATS / 4; j += THREADS)
        cpa16(ws0 + 4 * j, g_wt + 4 * j);
    cp_commit();

    // ---- fill x patch (zero at id/ih/iw == -1; upper bounds always ok) ----
    {
        const int d0 = 3 * odp - 1, h0 = 3 * ohp - 1, w0 = 6 * px - 1;
        for (int i = tid; i < IC * 200; i += THREADS) {
            int ic  = i / 200;
            int rem = i % 200;
            int ild = rem / 40;
            int ilh = (rem / 8) % 5;
            int ilw = rem % 8;
            int id = d0 + ild, ih = h0 + ilh, iw = w0 + ilw;
            float v = 0.0f;
            if (id >= 0 && ih >= 0 && iw >= 0)
                v = x[(((b * IC + ic) * 16 + id) * 32 + ih) * 32 + iw];
            ((float2*)xs)[i] = make_float2(v, v);
        }
    }
    cp_wait0();
    __syncthreads();

    // ---- warp geometry ----
    const int wid  = tid >> 5;
    const int lane = tid & 31;
    const int p    = c_p[wid];
    const int rh   = c_rh[wid];
    const int cell = c_cell[wid];
    const int ph = rh & 1;
    const int q  = rh >> 1;

    ull acc[3][6];
    #pragma unroll
    for (int ri = 0; ri < 3; ri++)
        #pragma unroll
        for (int r = 0; r < 6; r++)
            acc[ri][r] = 0ull;

    // ---- main loop: 16 chunks of 2 in-channels ----
    for (int c = 0; c < NCH; c++) {
        const float* cur = ws0 + (c & 1) * CHUNK_FLOATS;
        if (c + 1 < NCH) {
            float* nxt = ws0 + ((c + 1) & 1) * CHUNK_FLOATS;
            const float* src = g_wt + (c + 1) * CHUNK_FLOATS;
            for (int j = tid; j < CHUNK_FLOATS / 4; j += THREADS)
                cpa16(nxt + 4 * j, src + 4 * j);
        }
        cp_commit();

        #pragma unroll 1
        for (int icl = 0; icl < ICCH; icl++) {
            const int ic = c * ICCH + icl;
            const float* wic_l = cur + icl * WT_PER_IC + 2 * lane;
            const float* xc    = xs + ic * 400 + q * 16 + 6 * cell;
            if (p == 0) {
                if (ph == 0) {
                    if (cell == 0) compute_ic<0,0,0>(wic_l, xc, acc);
                    else           compute_ic<0,0,1>(wic_l, xc, acc);
                } else {
                    if (cell == 0) compute_ic<0,1,0>(wic_l, xc, acc);
                    else           compute_ic<0,1,1>(wic_l, xc, acc);
                }
            } else {
                if (ph == 0) {
                    if (cell == 0) compute_ic<1,0,0>(wic_l, xc, acc);
                    else           compute_ic<1,0,1>(wic_l, xc, acc);
                } else {
                    if (cell == 0) compute_ic<1,1,0>(wic_l, xc, acc);
                    else           compute_ic<1,1,1>(wic_l, xc, acc);
                }
            }
        }
        cp_wait0();
        __syncthreads();
    }

    // ---- reduction: per-warp max over its 18 positions -> red[wid][64] ----
    float* red = smem_dyn;     // reuse xs region: [24][64] + scratch @1536
    {
        float mlo = -3.4e38f, mhi = -3.4e38f;
        #pragma unroll
        for (int ri = 0; ri < 3; ri++)
            #pragma unroll
            for (int jr = 0; jr < 6; jr++) {
                ull a = acc[ri][jr];
                mlo = fmaxf(mlo, alo(a));
                mhi = fmaxf(mhi, ahi(a));
            }
        red[wid * OC + 2 * lane]     = mlo;
        red[wid * OC + 2 * lane + 1] = mhi;
    }
    __syncthreads();

    if (tid < 128) {
        const int cl = tid >> 6;     // cell
        const int oc = tid & 63;
        float v = -3.4e38f;
        #pragma unroll
        for (int w = 0; w < 24; w++)
            if (c_cell[w] == cl)
                v = fmaxf(v, red[w * OC + oc]);
        v += bias[oc];
        #pragma unroll
        for (int off = 16; off > 0; off >>= 1)
            v += __shfl_xor_sync(0xffffffffu, v, off);
        if ((tid & 31) == 0)
            red[1536 + (tid >> 5)] = v;   // 2 partials per cell
    }
    __syncthreads();

    if (tid < 2) {
        float s = red[1536 + 2 * tid] + red[1536 + 2 * tid + 1];
        out[((b * 5 + odp) * 10 + ohp) * 10 + 2 * px + tid] = s;
    }
}

// ---------------------------------------------------------------------------
extern "C" void kernel_launch(void* const* d_in, const int* in_sizes, int n_in,
                              void* d_out, int out_size) {
    const float* x    = (const float*)d_in[0];   // [16,32,16,32,32]
    const float* w    = (const float*)d_in[1];   // [32,64,5,5,5]
    const float* bias = (const float*)d_in[2];   // [64]
    float* out = (float*)d_out;                  // 8000

    wt_transpose_kernel<<<(WT_TOTAL + 255) / 256, 256>>>(w);

    cudaFuncSetAttribute(fused_kernel,
                         cudaFuncAttributeMaxDynamicSharedMemorySize,
                         SMEM_BYTES);
    dim3 grid(5, 10, 80);   // (w'-pair, oh', b*5 + od')
    fused_kernel<<<grid, THREADS, SMEM_BYTES>>>(x, bias, out);
}

// round 8
// speedup vs baseline: 3.4908x; 3.4908x over previous
#include <cuda_runtime.h>
#include <cstdint>

// ============================================================================
// Fused ConvTranspose3d(32->64,k=5,s=2,p=2) + MaxPool(2)+MaxPool(3) + ch-sum
// via legacy mma.sync TF32 implicit GEMM (sm_100-compatible; tcgen05 is not
// available because the harness targets plain sm_100).
//
// CTA = 2x2 (h,w) output cells, 1 d cell (grid 5x5x80 = 2000, 128 threads).
// 8 parity classes (pd,ph,pw); per class GEMM: M=108 positions (pad 128),
// N=64 oc, K=32 ic per tap, C accumulated in registers across the class's
// taps. Warp (mhalf,nhalf) computes a 64x32 quadrant: 4 m-tiles x 4 n-tiles
// of m16n8k8. A read directly from the x patch xs2[sp][ic] (stride 36 ->
// bank-conflict-minimal); B tiles [oc][ic] (stride 36, conflict-free)
// streamed per tap via double-buffered cp.async from pre-rounded TF32
// weights. Epilogue per class: C -> part[oc][pos] (stride 132, conflict-
// free) -> per-(cell,oc) max -> running register max; final bias+sum.
// ============================================================================

typedef unsigned int uint;

#define THREADS 128
#define XS_STRIDE 36
#define PS 132
// smem float offsets
#define XOFF 0                    // xs2 [320][36] = 11520
#define BOFF 11520                // Bt double buffer 2 x 2304 = 4608
#define POFF 16128                // part [64][132] = 8448
#define TOFF 24576                // tl_off[125], tl_tap[125]
#define SMEM_FLOATS 24832
#define SMEM_BYTES (SMEM_FLOATS * 4)   // 99328 B -> 2 CTAs/SM

__device__ __align__(16) float g_wtB[125 * 64 * 36];   // [tap][oc][ic(36)]

__device__ __forceinline__ float to_tf32(float v) {
    uint r;
    asm("cvt.rna.tf32.f32 %0, %1;" : "=r"(r) : "f"(v));
    return __uint_as_float(r);
}

// g_wtB[tap][oc][ic] <- tf32(w[ic][oc][kd][kh][kw])
__global__ void wt_prep_kernel(const float* __restrict__ w) {
    int idx = blockIdx.x * blockDim.x + threadIdx.x;
    if (idx >= 125 * 64 * 32) return;
    int ic  = idx & 31;
    int oc  = (idx >> 5) & 63;
    int tap = idx >> 11;
    g_wtB[(tap * 64 + oc) * XS_STRIDE + ic] =
        to_tf32(w[(ic * 64 + oc) * 125 + tap]);
}

__device__ __forceinline__ void cpa16(float* s, const float* g) {
    uint sa = (uint)__cvta_generic_to_shared(s);
    asm volatile("cp.async.cg.shared.global [%0], [%1], 16;" :: "r"(sa), "l"(g));
}
__device__ __forceinline__ void cp_commit() {
    asm volatile("cp.async.commit_group;");
}
__device__ __forceinline__ void cp_wait1() {
    asm volatile("cp.async.wait_group 1;" ::: "memory");
}
__device__ __forceinline__ void cp_wait0() {
    asm volatile("cp.async.wait_group 0;" ::: "memory");
}

__device__ __forceinline__ void mma_tf32(float* c, const uint* a, const uint* b) {
    asm volatile(
        "mma.sync.aligned.m16n8k8.row.col.f32.tf32.tf32.f32 "
        "{%0,%1,%2,%3}, {%4,%5,%6,%7}, {%8,%9}, {%0,%1,%2,%3};"
        : "+f"(c[0]), "+f"(c[1]), "+f"(c[2]), "+f"(c[3])
        : "r"(a[0]), "r"(a[1]), "r"(a[2]), "r"(a[3]), "r"(b[0]), "r"(b[1]));
}

__device__ __forceinline__ int spbase(int r) {
    if (r >= 108) return 0;
    return (r / 36) * 64 + ((r / 6) % 6) * 8 + (r % 6);
}

extern __shared__ float smem_dyn[];

__global__ void __launch_bounds__(THREADS, 2)
fused_kernel(const float* __restrict__ x,
             const float* __restrict__ bias,
             float* __restrict__ out) {
    float* xs2  = smem_dyn + XOFF;
    float* btb  = smem_dyn + BOFF;
    float* part = smem_dyn + POFF;
    int* tl_off = (int*)(smem_dyn + TOFF);
    int* tl_tap = tl_off + 125;

    const int owp = blockIdx.x;        // w cell-pair
    const int ohp = blockIdx.y;        // h cell-pair
    const int b   = blockIdx.z / 5;
    const int odp = blockIdx.z % 5;
    const int tid = threadIdx.x;
    const int wid = tid >> 5;
    const int lane = tid & 31;
    const int lm4 = lane & 3, ld4 = lane >> 2;
    const int mhalf = wid >> 1, nhalf = wid & 1;

    // ---- build tap list (thread 0) ----
    if (tid == 0) {
        int t = 0;
        for (int pd = 0; pd < 2; pd++)
            for (int ph = 0; ph < 2; ph++)
                for (int pw = 0; pw < 2; pw++)
                    for (int jd = 0; jd < 3 - pd; jd++)
                        for (int jh = 0; jh < 3 - ph; jh++)
                            for (int jw = 0; jw < 3 - pw; jw++) {
                                int kd = pd + 2 * jd, kh = ph + 2 * jh,
                                    kw = pw + 2 * jw;
                                tl_tap[t] = (kd * 5 + kh) * 5 + kw;
                                tl_off[t] = (2 - jd) * 64 + (2 - jh) * 8 +
                                            (2 - jw);
                                t++;
                            }
    }

    // ---- prefetch B tile for tap 0 (tap id 0) ----
    for (int q = tid; q < 576; q += THREADS)
        cpa16(btb + q * 4, g_wtB + q * 4);
    cp_commit();

    // ---- x patch fill: xs2[sp][ic], sp = ild*64 + ilh*8 + ilw ----
    {
        const int d0 = 3 * odp - 1, h0 = 6 * ohp - 1, w0 = 6 * owp - 1;
        for (int i = tid; i < 32 * 320; i += THREADS) {
            int ic = i / 320;
            int sp = i % 320;
            int ild = sp >> 6, ilh = (sp >> 3) & 7, ilw = sp & 7;
            int id = d0 + ild, ih = h0 + ilh, iw = w0 + ilw;
            float v = 0.0f;
            if (id >= 0 && ih >= 0 && iw >= 0)
                v = to_tf32(x[(((b * 32 + ic) * 16 + id) * 32 + ih) * 32 + iw]);
            xs2[sp * XS_STRIDE + ic] = v;
        }
    }
    __syncthreads();

    // ---- per-lane A row bases: j = mt*2 + hi ----
    int base36[8];
    #pragma unroll
    for (int mt = 0; mt < 4; mt++)
        #pragma unroll
        for (int hi = 0; hi < 2; hi++) {
            int r = mhalf * 64 + mt * 16 + hi * 8 + ld4;
            base36[mt * 2 + hi] = spbase(r) * XS_STRIDE;
        }

    const int CLS_NT[8] = {27, 18, 18, 12, 18, 12, 12, 8};
    float regAll[2] = {-3.4e38f, -3.4e38f};
    const float bv = bias[(wid & 1) * 32 + lane];
    int t = 0;

    for (int cls = 0; cls < 8; cls++) {
        const int ntap = CLS_NT[cls];
        float C[4][4][4];
        #pragma unroll
        for (int mt = 0; mt < 4; mt++)
            #pragma unroll
            for (int nt = 0; nt < 4; nt++)
                #pragma unroll
                for (int e = 0; e < 4; e++)
                    C[mt][nt][e] = 0.0f;

        for (int j = 0; j < ntap; j++, t++) {
            __syncthreads();   // protect buf (t+1)&1 from lagging readers
            if (t + 1 < 125) {
                const float* src = g_wtB + tl_tap[t + 1] * 2304;
                float* dst = btb + ((t + 1) & 1) * 2304;
                for (int q = tid; q < 576; q += THREADS)
                    cpa16(dst + q * 4, src + q * 4);
                cp_commit();
                cp_wait1();
            } else {
                cp_wait0();
            }
            __syncthreads();   // buf[t&1] visible to all

            const float* bt = btb + (t & 1) * 2304;
            const float* xb = xs2 + tl_off[t] * XS_STRIDE + lm4;
            const float* bp = bt + (nhalf * 32 + ld4) * XS_STRIDE + lm4;
            #pragma unroll
            for (int ks = 0; ks < 4; ks++) {
                const int ic0 = ks * 8;
                uint a[4][4], bb[4][2];
                #pragma unroll
                for (int mt = 0; mt < 4; mt++) {
                    a[mt][0] = *(const uint*)(xb + base36[mt * 2]     + ic0);
                    a[mt][1] = *(const uint*)(xb + base36[mt * 2 + 1] + ic0);
                    a[mt][2] = *(const uint*)(xb + base36[mt * 2]     + ic0 + 4);
                    a[mt][3] = *(const uint*)(xb + base36[mt * 2 + 1] + ic0 + 4);
                }
                #pragma unroll
                for (int nt = 0; nt < 4; nt++) {
                    bb[nt][0] = *(const uint*)(bp + nt * 8 * XS_STRIDE + ic0);
                    bb[nt][1] = *(const uint*)(bp + nt * 8 * XS_STRIDE + ic0 + 4);
                }
                #pragma unroll
                for (int mt = 0; mt < 4; mt++)
                    #pragma unroll
                    for (int nt = 0; nt < 4; nt++)
                        mma_tf32(C[mt][nt], a[mt], bb[nt]);
            }
        }

        // ---- class epilogue: C -> part[oc][pos] ----
        __syncthreads();
        #pragma unroll
        for (int mt = 0; mt < 4; mt++)
            #pragma unroll
            for (int nt = 0; nt < 4; nt++) {
                int col0 = nhalf * 32 + nt * 8 + 2 * lm4;
                int pos0 = mhalf * 64 + mt * 16 + ld4;
                part[col0 * PS + pos0]           = C[mt][nt][0];
                part[(col0 + 1) * PS + pos0]     = C[mt][nt][1];
                part[col0 * PS + pos0 + 8]       = C[mt][nt][2];
                part[(col0 + 1) * PS + pos0 + 8] = C[mt][nt][3];
            }
        __syncthreads();

        // reduce: thread -> oc = (wid&1)*32+lane, cells {slot, slot+2}
        {
            const int oc = (wid & 1) * 32 + lane;
            const int slot = wid >> 1;
            const float* pr = part + oc * PS;
            #pragma unroll
            for (int s = 0; s < 2; s++) {
                const int cell = slot + 2 * s;
                const int rb = (cell >> 1) * 18 + (cell & 1) * 3;
                float m = -3.4e38f;
                #pragma unroll
                for (int rd = 0; rd < 3; rd++)
                    #pragma unroll
                    for (int a2 = 0; a2 < 3; a2++)
                        #pragma unroll
                        for (int b2 = 0; b2 < 3; b2++)
                            m = fmaxf(m, pr[rb + rd * 36 + a2 * 6 + b2]);
                regAll[s] = fmaxf(regAll[s], m);
            }
        }
        // next loop iteration's first __syncthreads protects part reuse
    }

    // ---- final: +bias, sum over oc per cell ----
    __syncthreads();
    {
        float v0 = regAll[0] + bv;
        float v1 = regAll[1] + bv;
        #pragma unroll
        for (int off = 16; off > 0; off >>= 1) {
            v0 += __shfl_xor_sync(0xffffffffu, v0, off);
            v1 += __shfl_xor_sync(0xffffffffu, v1, off);
        }
        if (lane == 0) {
            const int slot = wid >> 1, half = wid & 1;
            part[slot * 2 + half] = v0;          // cell = slot
            part[(slot + 2) * 2 + half] = v1;    // cell = slot + 2
        }
    }
    __syncthreads();
    if (tid < 4) {
        float s = part[tid * 2] + part[tid * 2 + 1];
        const int ch = tid >> 1, cw = tid & 1;
        out[((b * 5 + odp) * 10 + 2 * ohp + ch) * 10 + 2 * owp + cw] = s;
    }
}

// ---------------------------------------------------------------------------
extern "C" void kernel_launch(void* const* d_in, const int* in_sizes, int n_in,
                              void* d_out, int out_size) {
    const float* x    = (const float*)d_in[0];   // [16,32,16,32,32]
    const float* w    = (const float*)d_in[1];   // [32,64,5,5,5]
    const float* bias = (const float*)d_in[2];   // [64]
    float* out = (float*)d_out;                  // 8000

    wt_prep_kernel<<<(125 * 64 * 32 + 255) / 256, 256>>>(w);

    cudaFuncSetAttribute(fused_kernel,
                         cudaFuncAttributeMaxDynamicSharedMemorySize,
                         SMEM_BYTES);
    dim3 grid(5, 5, 80);   // (w-pair, h-pair, b*5 + od')
    fused_kernel<<<grid, THREADS, SMEM_BYTES>>>(x, bias, out);
}

// round 9
// speedup vs baseline: 5.6202x; 1.6100x over previous
#include <cuda_runtime.h>
#include <cuda_fp16.h>
#include <cstdint>

// ============================================================================
// Fused ConvTranspose3d(32->64,k=5,s=2,p=2) + MaxPool(2)+MaxPool(3) + ch-sum
// via mma.sync FP16 implicit GEMM (m16n8k16, fp32 accum).
//
// fp16 mantissa == tf32 mantissa (10 bits) and all values are in range, so
// accuracy matches the tf32 version (~2e-5) while halving both the MMA
// instruction count and the LDS traffic.
//
// CTA = 2x2 (h,w) output cells (grid 5x5x80 = 2000, 128 threads, 3 CTAs/SM).
// 8 parity classes; per class GEMM: M=108 pos (pad 128), N=64 oc, K=32 ic
// per tap, fp32 C accumulated in registers over the class's taps.
// Warp (mhalf,nhalf) = 64x32 quadrant: 4 m-tiles x 4 n-tiles x 2 k-steps of
// m16n8k16. A read from fp16 x patch xs[sp][36]; B tiles [oc][36] fp16
// double-buffered via cp.async. Epilogue per class: C -> part[oc][pos] ->
// per-(cell,oc) max -> running register max; final bias+sum.
// ============================================================================

typedef unsigned int uint;

#define THREADS 128
#define XS_STRIDE 36            // fp16 units per sp row
#define PS 132
// smem float offsets
#define XOFF 0                  // xs 320 x 36 halfs = 5760 floats
#define BOFF 5760               // B double buffer 2 x 1152 floats
#define POFF 8064               // part [64][132] = 8448 floats
#define TOFF 16512              // tl_off[125], tl_tap[125]
#define SMEM_FLOATS 16768
#define SMEM_BYTES (SMEM_FLOATS * 4)   // 67072 B -> 3 CTAs/SM

__device__ __align__(16) __half g_wtH[125 * 64 * XS_STRIDE]; // [tap][oc][ic36]

// g_wtH[tap][oc][ic] <- fp16(w[ic][oc][kd][kh][kw])
__global__ void wt_prep_kernel(const float* __restrict__ w) {
    int idx = blockIdx.x * blockDim.x + threadIdx.x;
    if (idx >= 125 * 64 * 32) return;
    int ic  = idx & 31;
    int oc  = (idx >> 5) & 63;
    int tap = idx >> 11;
    g_wtH[(tap * 64 + oc) * XS_STRIDE + ic] =
        __float2half_rn(w[(ic * 64 + oc) * 125 + tap]);
}

__device__ __forceinline__ void cpa16(__half* s, const __half* g) {
    uint sa = (uint)__cvta_generic_to_shared(s);
    asm volatile("cp.async.cg.shared.global [%0], [%1], 16;" :: "r"(sa), "l"(g));
}
__device__ __forceinline__ void cp_commit() {
    asm volatile("cp.async.commit_group;");
}
__device__ __forceinline__ void cp_wait1() {
    asm volatile("cp.async.wait_group 1;" ::: "memory");
}
__device__ __forceinline__ void cp_wait0() {
    asm volatile("cp.async.wait_group 0;" ::: "memory");
}

__device__ __forceinline__ void mma_f16(float* c, const uint* a, const uint* b) {
    asm volatile(
        "mma.sync.aligned.m16n8k16.row.col.f32.f16.f16.f32 "
        "{%0,%1,%2,%3}, {%4,%5,%6,%7}, {%8,%9}, {%0,%1,%2,%3};"
        : "+f"(c[0]), "+f"(c[1]), "+f"(c[2]), "+f"(c[3])
        : "r"(a[0]), "r"(a[1]), "r"(a[2]), "r"(a[3]), "r"(b[0]), "r"(b[1]));
}

__device__ __forceinline__ int spbase(int r) {
    if (r >= 108) return 0;
    return (r / 36) * 64 + ((r / 6) % 6) * 8 + (r % 6);
}

extern __shared__ float smem_dyn[];

__global__ void __launch_bounds__(THREADS, 3)
fused_kernel(const float* __restrict__ x,
             const float* __restrict__ bias,
             float* __restrict__ out) {
    __half* xs  = (__half*)(smem_dyn + XOFF);     // [320][36] halfs
    __half* btb = (__half*)(smem_dyn + BOFF);     // 2 x 2304 halfs
    float* part = smem_dyn + POFF;
    int* tl_off = (int*)(smem_dyn + TOFF);
    int* tl_tap = tl_off + 125;

    const int owp = blockIdx.x;        // w cell-pair
    const int ohp = blockIdx.y;        // h cell-pair
    const int b   = blockIdx.z / 5;
    const int odp = blockIdx.z % 5;
    const int tid = threadIdx.x;
    const int wid = tid >> 5;
    const int lane = tid & 31;
    const int lm4 = lane & 3, ld4 = lane >> 2;
    const int mhalf = wid >> 1, nhalf = wid & 1;

    // ---- build tap list (thread 0) ----
    if (tid == 0) {
        int t = 0;
        for (int pd = 0; pd < 2; pd++)
            for (int ph = 0; ph < 2; ph++)
                for (int pw = 0; pw < 2; pw++)
                    for (int jd = 0; jd < 3 - pd; jd++)
                        for (int jh = 0; jh < 3 - ph; jh++)
                            for (int jw = 0; jw < 3 - pw; jw++) {
                                int kd = pd + 2 * jd, kh = ph + 2 * jh,
                                    kw = pw + 2 * jw;
                                tl_tap[t] = (kd * 5 + kh) * 5 + kw;
                                tl_off[t] = (2 - jd) * 64 + (2 - jh) * 8 +
                                            (2 - jw);
                                t++;
                            }
    }

    // ---- prefetch B tile for tap id 0 (first in tap list order) ----
    for (int q = tid; q < 288; q += THREADS)
        cpa16(btb + q * 8, g_wtH + q * 8);
    cp_commit();

    // ---- x patch fill: xs[sp][ic] fp16, sp = ild*64 + ilh*8 + ilw ----
    {
        const int d0 = 3 * odp - 1, h0 = 6 * ohp - 1, w0 = 6 * owp - 1;
        for (int i = tid; i < 320 * 16; i += THREADS) {
            int sp  = i >> 4;
            int icp = i & 15;                     // ic pair
            int ild = sp >> 6, ilh = (sp >> 3) & 7, ilw = sp & 7;
            int id = d0 + ild, ih = h0 + ilh, iw = w0 + ilw;
            float v0 = 0.0f, v1 = 0.0f;
            if (id >= 0 && ih >= 0 && iw >= 0) {
                const float* xp =
                    x + (((b * 32 + 2 * icp) * 16 + id) * 32 + ih) * 32 + iw;
                v0 = xp[0];
                v1 = xp[16 * 32 * 32];
            }
            *(__half2*)(xs + sp * XS_STRIDE + 2 * icp) =
                __floats2half2_rn(v0, v1);
        }
    }
    __syncthreads();

    // ---- per-lane A row bases (fp16 units): j = mt*2 + hi ----
    int base36[8];
    #pragma unroll
    for (int mt = 0; mt < 4; mt++)
        #pragma unroll
        for (int hi = 0; hi < 2; hi++) {
            int r = mhalf * 64 + mt * 16 + hi * 8 + ld4;
            base36[mt * 2 + hi] = spbase(r) * XS_STRIDE;
        }

    const int CLS_NT[8] = {27, 18, 18, 12, 18, 12, 12, 8};
    float regAll[2] = {-3.4e38f, -3.4e38f};
    const float bv = bias[(wid & 1) * 32 + lane];
    int t = 0;

    for (int cls = 0; cls < 8; cls++) {
        const int ntap = CLS_NT[cls];
        float C[4][4][4];
        #pragma unroll
        for (int mt = 0; mt < 4; mt++)
            #pragma unroll
            for (int nt = 0; nt < 4; nt++)
                #pragma unroll
                for (int e = 0; e < 4; e++)
                    C[mt][nt][e] = 0.0f;

        for (int j = 0; j < ntap; j++, t++) {
            __syncthreads();   // protect buf (t+1)&1 from lagging readers
            if (t + 1 < 125) {
                const __half* src = g_wtH + tl_tap[t + 1] * 2304;
                __half* dst = btb + ((t + 1) & 1) * 2304;
                for (int q = tid; q < 288; q += THREADS)
                    cpa16(dst + q * 8, src + q * 8);
                cp_commit();
                cp_wait1();
            } else {
                cp_wait0();
            }
            __syncthreads();   // buf[t&1] visible to all

            const __half* bt = btb + (t & 1) * 2304;
            const __half* xb = xs + tl_off[t] * XS_STRIDE + 2 * lm4;
            const __half* bp = bt + (nhalf * 32 + ld4) * XS_STRIDE + 2 * lm4;
            #pragma unroll
            for (int ks = 0; ks < 2; ks++) {
                const int ic0 = ks * 16;
                uint a[4][4], bb[4][2];
                #pragma unroll
                for (int mt = 0; mt < 4; mt++) {
                    a[mt][0] = *(const uint*)(xb + base36[mt * 2]     + ic0);
                    a[mt][1] = *(const uint*)(xb + base36[mt * 2 + 1] + ic0);
                    a[mt][2] = *(const uint*)(xb + base36[mt * 2]     + ic0 + 8);
                    a[mt][3] = *(const uint*)(xb + base36[mt * 2 + 1] + ic0 + 8);
                }
                #pragma unroll
                for (int nt = 0; nt < 4; nt++) {
                    bb[nt][0] = *(const uint*)(bp + nt * 8 * XS_STRIDE + ic0);
                    bb[nt][1] = *(const uint*)(bp + nt * 8 * XS_STRIDE + ic0 + 8);
                }
                #pragma unroll
                for (int mt = 0; mt < 4; mt++)
                    #pragma unroll
                    for (int nt = 0; nt < 4; nt++)
                        mma_f16(C[mt][nt], a[mt], bb[nt]);
            }
        }

        // ---- class epilogue: C -> part[oc][pos] ----
        __syncthreads();
        #pragma unroll
        for (int mt = 0; mt < 4; mt++)
            #pragma unroll
            for (int nt = 0; nt < 4; nt++) {
                int col0 = nhalf * 32 + nt * 8 + 2 * lm4;
                int pos0 = mhalf * 64 + mt * 16 + ld4;
                part[col0 * PS + pos0]           = C[mt][nt][0];
                part[(col0 + 1) * PS + pos0]     = C[mt][nt][1];
                part[col0 * PS + pos0 + 8]       = C[mt][nt][2];
                part[(col0 + 1) * PS + pos0 + 8] = C[mt][nt][3];
            }
        __syncthreads();

        // reduce: thread -> oc = (wid&1)*32+lane, cells {slot, slot+2}
        {
            const int oc = (wid & 1) * 32 + lane;
            const int slot = wid >> 1;
            const float* pr = part + oc * PS;
            #pragma unroll
            for (int s = 0; s < 2; s++) {
                const int cell = slot + 2 * s;
                const int rb = (cell >> 1) * 18 + (cell & 1) * 3;
                float m = -3.4e38f;
                #pragma unroll
                for (int rd = 0; rd < 3; rd++)
                    #pragma unroll
                    for (int a2 = 0; a2 < 3; a2++)
                        #pragma unroll
                        for (int b2 = 0; b2 < 3; b2++)
                            m = fmaxf(m, pr[rb + rd * 36 + a2 * 6 + b2]);
                regAll[s] = fmaxf(regAll[s], m);
            }
        }
        // next iteration's first __syncthreads protects part reuse
    }

    // ---- final: +bias, sum over oc per cell ----
    __syncthreads();
    {
        float v0 = regAll[0] + bv;
        float v1 = regAll[1] + bv;
        #pragma unroll
        for (int off = 16; off > 0; off >>= 1) {
            v0 += __shfl_xor_sync(0xffffffffu, v0, off);
            v1 += __shfl_xor_sync(0xffffffffu, v1, off);
        }
        if (lane == 0) {
            const int slot = wid >> 1, half = wid & 1;
            part[slot * 2 + half] = v0;          // cell = slot
            part[(slot + 2) * 2 + half] = v1;    // cell = slot + 2
        }
    }
    __syncthreads();
    if (tid < 4) {
        float s = part[tid * 2] + part[tid * 2 + 1];
        const int ch = tid >> 1, cw = tid & 1;
        out[((b * 5 + odp) * 10 + 2 * ohp + ch) * 10 + 2 * owp + cw] = s;
    }
}

// ---------------------------------------------------------------------------
extern "C" void kernel_launch(void* const* d_in, const int* in_sizes, int n_in,
                              void* d_out, int out_size) {
    const float* x    = (const float*)d_in[0];   // [16,32,16,32,32]
    const float* w    = (const float*)d_in[1];   // [32,64,5,5,5]
    const float* bias = (const float*)d_in[2];   // [64]
    float* out = (float*)d_out;                  // 8000

    wt_prep_kernel<<<(125 * 64 * 32 + 255) / 256, 256>>>(w);

    cudaFuncSetAttribute(fused_kernel,
                         cudaFuncAttributeMaxDynamicSharedMemorySize,
                         SMEM_BYTES);
    dim3 grid(5, 5, 80);   // (w-pair, h-pair, b*5 + od')
    fused_kernel<<<grid, THREADS, SMEM_BYTES>>>(x, bias, out);
}

// round 10
// speedup vs baseline: 6.3065x; 1.1221x over previous
#include <cuda_runtime.h>
#include <cuda_fp16.h>
#include <cstdint>

// ============================================================================
// Fused ConvTranspose3d(32->64,k=5,s=2,p=2) + MaxPool(2)+MaxPool(3) + ch-sum
// via mma.sync FP16 implicit GEMM (m16n8k16, fp32 accum), ldmatrix loads.
//
// CTA = 2x2 (h,w) cells (grid 5x5x80 = 2000, 128 threads, 3 CTAs/SM).
// 8 parity classes; per class GEMM: M=108 pos (pad 128), N=64 oc, K=32 ic
// per tap, fp32 C in registers across the class's taps.
// x patch: xs[sp] rows of 32 ic halfs, 80B row stride, 16B chunks XOR-
// swizzled by (sp>>3)&3 -> ldmatrix.x4 A loads are bank-conflict-free.
// B tiles [oc][ic] at 80B stride (consecutive oc rows -> conflict-free),
// double-buffered via cp.async. Epilogue part[oc][PS=133] (133 = 5 mod 32,
// conflict-free reduce reads).
// ============================================================================

typedef unsigned int uint;

#define THREADS 128
#define PS 133
// smem float offsets
#define XOFF 0                  // xs 320 rows x 80B = 25600B = 6400 floats
#define BOFF 6400               // B double buffer 2 x 5120B = 2560 floats
#define POFF 8960               // part [64][133] = 8512 floats
#define TOFF 17472              // tl_off[125], tl_tap[125]
#define SMEM_FLOATS 17728
#define SMEM_BYTES (SMEM_FLOATS * 4)   // 70912 B -> 3 CTAs/SM

__device__ __align__(16) __half g_wtH[125 * 64 * 32];   // [tap][oc][ic32]

// g_wtH[tap][oc][ic] <- fp16(w[ic][oc][kd][kh][kw])
__global__ void wt_prep_kernel(const float* __restrict__ w) {
    int idx = blockIdx.x * blockDim.x + threadIdx.x;
    if (idx >= 125 * 64 * 32) return;
    int ic  = idx & 31;
    int oc  = (idx >> 5) & 63;
    int tap = idx >> 11;
    g_wtH[(tap * 64 + oc) * 32 + ic] =
        __float2half_rn(w[(ic * 64 + oc) * 125 + tap]);
}

__device__ __forceinline__ void cpa16(char* s, const void* g) {
    uint sa = (uint)__cvta_generic_to_shared(s);
    asm volatile("cp.async.cg.shared.global [%0], [%1], 16;" :: "r"(sa), "l"(g));
}
__device__ __forceinline__ void cp_commit() {
    asm volatile("cp.async.commit_group;");
}
__device__ __forceinline__ void cp_wait1() {
    asm volatile("cp.async.wait_group 1;" ::: "memory");
}
__device__ __forceinline__ void cp_wait0() {
    asm volatile("cp.async.wait_group 0;" ::: "memory");
}

__device__ __forceinline__ void ldm_x4(uint* r, uint addr) {
    asm volatile("ldmatrix.sync.aligned.m8n8.x4.shared.b16 {%0,%1,%2,%3}, [%4];"
                 : "=r"(r[0]), "=r"(r[1]), "=r"(r[2]), "=r"(r[3]) : "r"(addr));
}
__device__ __forceinline__ void ldm_x2(uint* r, uint addr) {
    asm volatile("ldmatrix.sync.aligned.m8n8.x2.shared.b16 {%0,%1}, [%2];"
                 : "=r"(r[0]), "=r"(r[1]) : "r"(addr));
}

__device__ __forceinline__ void mma_f16(float* c, const uint* a, const uint* b) {
    asm volatile(
        "mma.sync.aligned.m16n8k16.row.col.f32.f16.f16.f32 "
        "{%0,%1,%2,%3}, {%4,%5,%6,%7}, {%8,%9}, {%0,%1,%2,%3};"
        : "+f"(c[0]), "+f"(c[1]), "+f"(c[2]), "+f"(c[3])
        : "r"(a[0]), "r"(a[1]), "r"(a[2]), "r"(a[3]), "r"(b[0]), "r"(b[1]));
}

__device__ __forceinline__ int spbase(int r) {
    if (r >= 108) return 0;
    return (r / 36) * 64 + ((r / 6) % 6) * 8 + (r % 6);
}

extern __shared__ float smem_dyn[];

__global__ void __launch_bounds__(THREADS, 3)
fused_kernel(const float* __restrict__ x,
             const float* __restrict__ bias,
             float* __restrict__ out) {
    char*  xsb  = (char*)(smem_dyn + XOFF);       // x rows, 80B stride
    char*  btb  = (char*)(smem_dyn + BOFF);       // 2 x 5120B B tiles
    float* part = smem_dyn + POFF;
    int* tl_off = (int*)(smem_dyn + TOFF);
    int* tl_tap = tl_off + 125;

    const int owp = blockIdx.x;
    const int ohp = blockIdx.y;
    const int b   = blockIdx.z / 5;
    const int odp = blockIdx.z % 5;
    const int tid = threadIdx.x;
    const int wid = tid >> 5;
    const int lane = tid & 31;
    const int mhalf = wid >> 1, nhalf = wid & 1;

    const uint xs_u = (uint)__cvta_generic_to_shared(xsb);
    const uint bt_u0 = (uint)__cvta_generic_to_shared(btb);

    // ---- build tap list (thread 0) ----
    if (tid == 0) {
        int t = 0;
        for (int pd = 0; pd < 2; pd++)
            for (int ph = 0; ph < 2; ph++)
                for (int pw = 0; pw < 2; pw++)
                    for (int jd = 0; jd < 3 - pd; jd++)
                        for (int jh = 0; jh < 3 - ph; jh++)
                            for (int jw = 0; jw < 3 - pw; jw++) {
                                int kd = pd + 2 * jd, kh = ph + 2 * jh,
                                    kw = pw + 2 * jw;
                                tl_tap[t] = (kd * 5 + kh) * 5 + kw;
                                tl_off[t] = (2 - jd) * 64 + (2 - jh) * 8 +
                                            (2 - jw);
                                t++;
                            }
    }

    // ---- prefetch B tile for tap id 0 (64 rows x 4 chunks) ----
    for (int q = tid; q < 256; q += THREADS) {
        int oc = q >> 2, c = q & 3;
        cpa16(btb + oc * 80 + c * 16, g_wtH + oc * 32 + c * 8);
    }
    cp_commit();

    // ---- x patch fill: row sp (80B stride), chunk-XOR swizzle ----
    {
        const int d0 = 3 * odp - 1, h0 = 6 * ohp - 1, w0 = 6 * owp - 1;
        for (int i = tid; i < 320 * 16; i += THREADS) {
            int sp  = i >> 4;
            int icp = i & 15;                     // ic pair 0..15
            int ild = sp >> 6, ilh = (sp >> 3) & 7, ilw = sp & 7;
            int id = d0 + ild, ih = h0 + ilh, iw = w0 + ilw;
            float v0 = 0.0f, v1 = 0.0f;
            if (id >= 0 && ih >= 0 && iw >= 0) {
                const float* xp =
                    x + (((b * 32 + 2 * icp) * 16 + id) * 32 + ih) * 32 + iw;
                v0 = xp[0];
                v1 = xp[16 * 32 * 32];
            }
            uint u = ((uint)sp >> 3) & 3u;
            uint c = (uint)(icp >> 2);
            uint addr = (uint)sp * 80u + (((c ^ u) << 4) | ((uint)(icp & 3) << 2));
            *(__half2*)(xsb + addr) = __floats2half2_rn(v0, v1);
        }
    }
    __syncthreads();

    // ---- per-lane fragment geometry ----
    const int grpA = lane >> 4;                   // A k-half (chunk bit0)
    int sp0[4];
    #pragma unroll
    for (int mt = 0; mt < 4; mt++) {
        int r = mhalf * 64 + mt * 16 + ((lane >> 3) & 1) * 8 + (lane & 7);
        sp0[mt] = spbase(r);
    }
    uint rB[4];
    {
        const int l15 = lane & 15;
        const int grpB = l15 >> 3;                // B k-half
        #pragma unroll
        for (int nt = 0; nt < 4; nt++) {
            int row = nhalf * 32 + nt * 8 + (l15 & 7);
            rB[nt] = (uint)row * 80u + (uint)grpB * 16u;
        }
    }

    const int CLS_NT[8] = {27, 18, 18, 12, 18, 12, 12, 8};
    float regAll[2] = {-3.4e38f, -3.4e38f};
    const float bv = bias[(wid & 1) * 32 + lane];
    int t = 0;

    for (int cls = 0; cls < 8; cls++) {
        const int ntap = CLS_NT[cls];
        float C[4][4][4];
        #pragma unroll
        for (int mt = 0; mt < 4; mt++)
            #pragma unroll
            for (int nt = 0; nt < 4; nt++)
                #pragma unroll
                for (int e = 0; e < 4; e++)
                    C[mt][nt][e] = 0.0f;

        for (int j = 0; j < ntap; j++, t++) {
            __syncthreads();   // protect buf (t+1)&1 from lagging readers
            if (t + 1 < 125) {
                const __half* src = g_wtH + tl_tap[t + 1] * 2048;
                char* dst = btb + ((t + 1) & 1) * 5120;
                for (int q = tid; q < 256; q += THREADS) {
                    int oc = q >> 2, c = q & 3;
                    cpa16(dst + oc * 80 + c * 16, src + oc * 32 + c * 8);
                }
                cp_commit();
                cp_wait1();
            } else {
                cp_wait0();
            }
            __syncthreads();   // buf[t&1] visible to all

            const uint bt_u = bt_u0 + (uint)((t & 1) * 5120);
            const int off = tl_off[t];
            uint A0[4], A1[4];
            #pragma unroll
            for (int mt = 0; mt < 4; mt++) {
                int sp = sp0[mt] + off;
                uint u = ((uint)sp >> 3) & 3u;
                uint cx = ((uint)grpA ^ u) << 4;
                uint base = xs_u + (uint)sp * 80u;
                A0[mt] = base + cx;
                A1[mt] = base + (cx ^ 32u);
            }

            uint a[4][4], bb[4][2];
            // ks = 0
            #pragma unroll
            for (int mt = 0; mt < 4; mt++) ldm_x4(a[mt], A0[mt]);
            #pragma unroll
            for (int nt = 0; nt < 4; nt++) ldm_x2(bb[nt], bt_u + rB[nt]);
            #pragma unroll
            for (int mt = 0; mt < 4; mt++)
                #pragma unroll
                for (int nt = 0; nt < 4; nt++)
                    mma_f16(C[mt][nt], a[mt], bb[nt]);
            // ks = 1
            #pragma unroll
            for (int mt = 0; mt < 4; mt++) ldm_x4(a[mt], A1[mt]);
            #pragma unroll
            for (int nt = 0; nt < 4; nt++) ldm_x2(bb[nt], bt_u + rB[nt] + 32u);
            #pragma unroll
            for (int mt = 0; mt < 4; mt++)
                #pragma unroll
                for (int nt = 0; nt < 4; nt++)
                    mma_f16(C[mt][nt], a[mt], bb[nt]);
        }

        // ---- class epilogue: C -> part[oc][pos] (PS=133) ----
        __syncthreads();
        {
            const int lm4 = lane & 3, ld4 = lane >> 2;
            #pragma unroll
            for (int mt = 0; mt < 4; mt++)
                #pragma unroll
                for (int nt = 0; nt < 4; nt++) {
                    int col0 = nhalf * 32 + nt * 8 + 2 * lm4;
                    int pos0 = mhalf * 64 + mt * 16 + ld4;
                    part[col0 * PS + pos0]           = C[mt][nt][0];
                    part[(col0 + 1) * PS + pos0]     = C[mt][nt][1];
                    part[col0 * PS + pos0 + 8]       = C[mt][nt][2];
                    part[(col0 + 1) * PS + pos0 + 8] = C[mt][nt][3];
                }
        }
        __syncthreads();

        // reduce: thread -> oc = (wid&1)*32+lane, cells {slot, slot+2}
        {
            const int oc = (wid & 1) * 32 + lane;
            const int slot = wid >> 1;
            const float* pr = part + oc * PS;
            #pragma unroll
            for (int s = 0; s < 2; s++) {
                const int cell = slot + 2 * s;
                const int rb = (cell >> 1) * 18 + (cell & 1) * 3;
                float m = -3.4e38f;
                #pragma unroll
                for (int rd = 0; rd < 3; rd++)
                    #pragma unroll
                    for (int a2 = 0; a2 < 3; a2++)
                        #pragma unroll
                        for (int b2 = 0; b2 < 3; b2++)
                            m = fmaxf(m, pr[rb + rd * 36 + a2 * 6 + b2]);
                regAll[s] = fmaxf(regAll[s], m);
            }
        }
        // next iteration's first __syncthreads protects part reuse
    }

    // ---- final: +bias, sum over oc per cell ----
    __syncthreads();
    {
        float v0 = regAll[0] + bv;
        float v1 = regAll[1] + bv;
        #pragma unroll
        for (int off = 16; off > 0; off >>= 1) {
            v0 += __shfl_xor_sync(0xffffffffu, v0, off);
            v1 += __shfl_xor_sync(0xffffffffu, v1, off);
        }
        if (lane == 0) {
            const int slot = wid >> 1, half = wid & 1;
            part[slot * 2 + half] = v0;          // cell = slot
            part[(slot + 2) * 2 + half] = v1;    // cell = slot + 2
        }
    }
    __syncthreads();
    if (tid < 4) {
        float s = part[tid * 2] + part[tid * 2 + 1];
        const int ch = tid >> 1, cw = tid & 1;
        out[((b * 5 + odp) * 10 + 2 * ohp + ch) * 10 + 2 * owp + cw] = s;
    }
}

// ---------------------------------------------------------------------------
extern "C" void kernel_launch(void* const* d_in, const int* in_sizes, int n_in,
                              void* d_out, int out_size) {
    const float* x    = (const float*)d_in[0];   // [16,32,16,32,32]
    const float* w    = (const float*)d_in[1];   // [32,64,5,5,5]
    const float* bias = (const float*)d_in[2];   // [64]
    float* out = (float*)d_out;                  // 8000

    wt_prep_kernel<<<(125 * 64 * 32 + 255) / 256, 256>>>(w);

    cudaFuncSetAttribute(fused_kernel,
                         cudaFuncAttributeMaxDynamicSharedMemorySize,
                         SMEM_BYTES);
    dim3 grid(5, 5, 80);   // (w-pair, h-pair, b*5 + od')
    fused_kernel<<<grid, THREADS, SMEM_BYTES>>>(x, bias, out);
}

// round 11
// speedup vs baseline: 8.1918x; 1.2990x over previous
#include <cuda_runtime.h>
#include <cuda_fp16.h>
#include <cstdint>

// ============================================================================
// Fused ConvTranspose3d(32->64,k=5,s=2,p=2) + MaxPool(2)+MaxPool(3) + ch-sum
// via mma.sync FP16 implicit GEMM (m16n8k16, fp32 accum), ldmatrix loads.
//
// R11: CTA = 1 od x 2 oh x 5 ow cells (grid 2x25x16 = 800, 192 thr, 6 warps,
// 2 CTAs/SM). Per parity class (pd,ph,pw): GEMM M=288 positions
// (ri 3 x rhi 6 x j 16, j = w index, j=15 junk), N=64 oc, K=32 ic per tap.
// M row order puts j innermost -> each ldmatrix 8x8 matrix reads 8
// CONSECUTIVE xs rows (only ilw varies) -> with 80B row stride the 16B
// groups (5R+c mod 8) are all distinct: bank-conflict-free by construction.
// Warp = 3 m-tiles (ri = wid>>1 fixed, rhi = 3*(wid&1)+mt) x all 8 n-tiles.
// B tiles [oc][ic] at 80B stride, double-buffered cp.async.
// Epilogue per class: 3 stages (by ri): C -> part[oc][PS=101] -> per-cell
// max into regAll[4]; final bias+sum over oc.
// ============================================================================

typedef unsigned int uint;

#define THREADS 192
#define PS 101
// smem byte offsets
#define B_OFF    57600           // xs: 720 rows x 80B
#define PART_OFF 67840           // B: 2 x 5120B
#define TL_OFF   93696           // part: 64*101*4 = 25856B
#define SMEM_BYTES 94720

__device__ __align__(16) __half g_wtH[125 * 64 * 32];   // [tap][oc][ic32]

// g_wtH[tap][oc][ic] <- fp16(w[ic][oc][kd][kh][kw])
__global__ void wt_prep_kernel(const float* __restrict__ w) {
    int idx = blockIdx.x * blockDim.x + threadIdx.x;
    if (idx >= 125 * 64 * 32) return;
    int ic  = idx & 31;
    int oc  = (idx >> 5) & 63;
    int tap = idx >> 11;
    g_wtH[(tap * 64 + oc) * 32 + ic] =
        __float2half_rn(w[(ic * 64 + oc) * 125 + tap]);
}

__device__ __forceinline__ void cpa16(char* s, const void* g) {
    uint sa = (uint)__cvta_generic_to_shared(s);
    asm volatile("cp.async.cg.shared.global [%0], [%1], 16;" :: "r"(sa), "l"(g));
}
__device__ __forceinline__ void cp_commit() {
    asm volatile("cp.async.commit_group;");
}
__device__ __forceinline__ void cp_wait1() {
    asm volatile("cp.async.wait_group 1;" ::: "memory");
}
__device__ __forceinline__ void cp_wait0() {
    asm volatile("cp.async.wait_group 0;" ::: "memory");
}

__device__ __forceinline__ void ldm_x4(uint* r, uint addr) {
    asm volatile("ldmatrix.sync.aligned.m8n8.x4.shared.b16 {%0,%1,%2,%3}, [%4];"
                 : "=r"(r[0]), "=r"(r[1]), "=r"(r[2]), "=r"(r[3]) : "r"(addr));
}

__device__ __forceinline__ void mma_f16(float* c, const uint* a, const uint* b) {
    asm volatile(
        "mma.sync.aligned.m16n8k16.row.col.f32.f16.f16.f32 "
        "{%0,%1,%2,%3}, {%4,%5,%6,%7}, {%8,%9}, {%0,%1,%2,%3};"
        : "+f"(c[0]), "+f"(c[1]), "+f"(c[2]), "+f"(c[3])
        : "r"(a[0]), "r"(a[1]), "r"(a[2]), "r"(a[3]), "r"(b[0]), "r"(b[1]));
}

extern __shared__ char smem_raw[];

__global__ void __launch_bounds__(THREADS, 2)
fused_kernel(const float* __restrict__ x,
             const float* __restrict__ bias,
             float* __restrict__ out) {
    char*  xsb  = smem_raw;                     // x rows: R in [0,720), 80B
    char*  btb  = smem_raw + B_OFF;             // B double buffer
    float* part = (float*)(smem_raw + PART_OFF);
    int* tl_tap   = (int*)(smem_raw + TL_OFF);
    int* tl_abase = tl_tap + 125;

    const int whp = blockIdx.x;                 // w half-line (5 ow cells)
    const int odp = blockIdx.y / 5;
    const int ohp = blockIdx.y % 5;
    const int b   = blockIdx.z;
    const int tid  = threadIdx.x;
    const int wid  = tid >> 5;
    const int lane = tid & 31;
    const int lane7 = lane & 7;
    const int lm4 = lane & 3, ld4 = lane >> 2;

    const uint xs_u  = (uint)__cvta_generic_to_shared(xsb);
    const uint bt_u0 = (uint)__cvta_generic_to_shared(btb);

    // ---- tap tables (thread 0): grouped by class (pd,ph,pw) ----
    if (tid == 0) {
        int t = 0;
        for (int pd = 0; pd < 2; pd++)
            for (int ph = 0; ph < 2; ph++)
                for (int pw = 0; pw < 2; pw++)
                    for (int jd = 0; jd < 3 - pd; jd++)
                        for (int jh = 0; jh < 3 - ph; jh++)
                            for (int jw = 0; jw < 3 - pw; jw++) {
                                int kd = pd + 2 * jd, kh = ph + 2 * jh,
                                    kw = pw + 2 * jw;
                                tl_tap[t] = (kd * 5 + kh) * 5 + kw;
                                tl_abase[t] =
                                    ((2 - jd) * 144 + (2 - jh) * 18 +
                                     (2 - jw)) * 80;
                                t++;
                            }
    }

    // ---- prefetch B tile for tap id 0 (list head is tap 0) ----
    for (int q = tid; q < 256; q += THREADS)
        cpa16(btb + (q >> 2) * 80 + (q & 3) * 16,
              g_wtH + (q >> 2) * 32 + (q & 3) * 8);
    cp_commit();

    // ---- x patch fill: row R = (ild*8 + ilh)*18 + ilw, 32 ic halfs ----
    {
        const int d0 = 3 * odp - 1, h0 = 6 * ohp - 1, w0 = 15 * whp - 1;
        for (int icp = 0; icp < 16; icp++) {
            const float* xpl = x + (size_t)(b * 32 + 2 * icp) * 16384;
            for (int R = tid; R < 720; R += THREADS) {
                int ild = R / 144, rem = R % 144;
                int ilh = rem / 18, ilw = rem % 18;
                int id = d0 + ild, ih = h0 + ilh, iw = w0 + ilw;
                float v0 = 0.0f, v1 = 0.0f;
                if (id >= 0 && ih >= 0 && iw >= 0) {
                    const float* p = xpl + (id * 32 + ih) * 32 + iw;
                    v0 = p[0];
                    v1 = p[16384];
                }
                *(__half2*)(xsb + R * 80 + icp * 4) =
                    __floats2half2_rn(v0, v1);
            }
        }
    }
    __syncthreads();

    // ---- per-lane / per-warp address constants ----
    const uint laneA = (uint)(lane7 * 80 + ((lane >> 3) & 1) * 640 +
                              (lane >> 4) * 16);
    const uint laneB = (uint)(((lane >> 4) * 8 + lane7) * 80 +
                              ((lane >> 3) & 1) * 16);
    const uint wA = (uint)((wid >> 1) * 11520 + (wid & 1) * 4320);

    const int CLS_NT[8] = {27, 18, 18, 12, 18, 12, 12, 8};
    float regAll[4] = {-3.4e38f, -3.4e38f, -3.4e38f, -3.4e38f};
    int t = 0;

    #pragma unroll 1
    for (int cls = 0; cls < 8; cls++) {
        float C[3][8][4];
        #pragma unroll
        for (int mt = 0; mt < 3; mt++)
            #pragma unroll
            for (int nt = 0; nt < 8; nt++)
                #pragma unroll
                for (int e = 0; e < 4; e++)
                    C[mt][nt][e] = 0.0f;

        const int ntap = CLS_NT[cls];
        #pragma unroll 1
        for (int j = 0; j < ntap; j++, t++) {
            __syncthreads();   // protect write buffer from lagging readers
            if (t + 1 < 125) {
                const __half* src = g_wtH + tl_tap[t + 1] * 2048;
                char* dst = btb + ((t + 1) & 1) * 5120;
                for (int q = tid; q < 256; q += THREADS)
                    cpa16(dst + (q >> 2) * 80 + (q & 3) * 16,
                          src + (q >> 2) * 32 + (q & 3) * 8);
                cp_commit();
                cp_wait1();
            } else {
                cp_wait0();
            }
            __syncthreads();   // buf[t&1] visible

            const uint bt_u = bt_u0 + (uint)((t & 1) * 5120) + laneB;
            const uint aa = xs_u + (uint)tl_abase[t] + wA + laneA;
            #pragma unroll
            for (int ks = 0; ks < 2; ks++) {
                uint bfr[8][2];
                #pragma unroll
                for (int q = 0; q < 4; q++) {
                    uint r[4];
                    ldm_x4(r, bt_u + (uint)(q * 1280 + ks * 32));
                    bfr[2 * q][0] = r[0];  bfr[2 * q][1] = r[1];
                    bfr[2 * q + 1][0] = r[2]; bfr[2 * q + 1][1] = r[3];
                }
                #pragma unroll
                for (int mt = 0; mt < 3; mt++) {
                    uint a[4];
                    ldm_x4(a, aa + (uint)(mt * 1440 + ks * 32));
                    #pragma unroll
                    for (int nt = 0; nt < 8; nt++)
                        mma_f16(C[mt][nt], a, bfr[nt]);
                }
            }
        }

        // ---- class epilogue: 3 stages by ri ----
        #pragma unroll 1
        for (int s = 0; s < 3; s++) {
            __syncthreads();
            if ((wid >> 1) == s) {
                const int rb = 3 * (wid & 1);
                #pragma unroll
                for (int mt = 0; mt < 3; mt++)
                    #pragma unroll
                    for (int nt = 0; nt < 8; nt++) {
                        int oc0 = nt * 8 + 2 * lm4;
                        int pos0 = (rb + mt) * 16 + ld4;
                        part[oc0 * PS + pos0]           = C[mt][nt][0];
                        part[(oc0 + 1) * PS + pos0]     = C[mt][nt][1];
                        part[oc0 * PS + pos0 + 8]       = C[mt][nt][2];
                        part[(oc0 + 1) * PS + pos0 + 8] = C[mt][nt][3];
                    }
            }
            __syncthreads();
            {
                const int oc = tid & 63, slot = tid >> 6;
                const float* pr = part + oc * PS;
                #pragma unroll
                for (int k = 0; k < 4; k++) {
                    int cc = slot + 3 * k;
                    if (cc < 10) {
                        int ch = (cc >= 5) ? 1 : 0;
                        int cw = cc - 5 * ch;
                        const float* pb = pr + ch * 48 + 3 * cw;
                        float m = regAll[k];
                        #pragma unroll
                        for (int u = 0; u < 3; u++)
                            #pragma unroll
                            for (int v = 0; v < 3; v++)
                                m = fmaxf(m, pb[u * 16 + v]);
                        regAll[k] = m;
                    }
                }
            }
        }
    }

    // ---- final: +bias, sum over oc per cell ----
    __syncthreads();
    float* red = part;    // [10][64]
    {
        const int oc = tid & 63, slot = tid >> 6;
        #pragma unroll
        for (int k = 0; k < 4; k++) {
            int cc = slot + 3 * k;
            if (cc < 10) red[cc * 64 + oc] = regAll[k] + bias[oc];
        }
    }
    __syncthreads();
    for (int cc = wid; cc < 10; cc += 6) {
        float v = red[cc * 64 + lane] + red[cc * 64 + 32 + lane];
        #pragma unroll
        for (int off = 16; off > 0; off >>= 1)
            v += __shfl_xor_sync(0xffffffffu, v, off);
        if (lane == 0) {
            int ch = (cc >= 5) ? 1 : 0;
            int cw = cc - 5 * ch;
            out[((b * 5 + odp) * 10 + 2 * ohp + ch) * 10 + 5 * whp + cw] = v;
        }
    }
}

// ---------------------------------------------------------------------------
extern "C" void kernel_launch(void* const* d_in, const int* in_sizes, int n_in,
                              void* d_out, int out_size) {
    const float* x    = (const float*)d_in[0];   // [16,32,16,32,32]
    const float* w    = (const float*)d_in[1];   // [32,64,5,5,5]
    const float* bias = (const float*)d_in[2];   // [64]
    float* out = (float*)d_out;                  // 8000

    wt_prep_kernel<<<(125 * 64 * 32 + 255) / 256, 256>>>(w);

    cudaFuncSetAttribute(fused_kernel,
                         cudaFuncAttributeMaxDynamicSharedMemorySize,
                         SMEM_BYTES);
    dim3 grid(2, 25, 16);   // (w half-line, odp*5+ohp, b)
    fused_kernel<<<grid, THREADS, SMEM_BYTES>>>(x, bias, out);
}